// round 1
// baseline (speedup 1.0000x reference)
#include <cuda_runtime.h>
#include <math_constants.h>

#define BATCH 32
#define SEQ   2048
#define CDIM  384
#define HDIM  64
#define M_TOT (BATCH*SEQ)

// scratch: q (pre-scaled), k, v  — [B*T, H] row-major
__device__ __align__(16) float g_k[M_TOT*HDIM];
__device__ __align__(16) float g_q[M_TOT*HDIM];
__device__ __align__(16) float g_v[M_TOT*HDIM];

// ---------------------------------------------------------------------------
// Projection: k/q/v = x @ W{k,q,v}.  M=65536, K=384, N=64.
// Block = 64 rows x 64 cols, 256 threads, 4x4 micro-tile per thread, all three
// weights computed together sharing the x fragment.
// ---------------------------------------------------------------------------
__global__ __launch_bounds__(256) void proj_kernel(
    const float* __restrict__ x, const float* __restrict__ Wk,
    const float* __restrict__ Wq, const float* __restrict__ Wv)
{
    __shared__ __align__(16) float xs[64][33];     // [row][c-chunk]
    __shared__ __align__(16) float ws[3][32][68];  // [w][c-chunk][col], stride 68 for f4

    const int tid = threadIdx.x;
    const int tx = tid & 15;        // col group (4 cols)
    const int ty = tid >> 4;        // row group (4 rows)
    const int row0 = blockIdx.x * 64;

    float acc[3][4][4];
#pragma unroll
    for (int w = 0; w < 3; w++)
#pragma unroll
        for (int i = 0; i < 4; i++)
#pragma unroll
            for (int j = 0; j < 4; j++) acc[w][i][j] = 0.f;

    for (int c0 = 0; c0 < CDIM; c0 += 32) {
        // load x tile 64x32 (coalesced)
#pragma unroll
        for (int t = 0; t < 8; t++) {
            int idx = tid + t * 256;          // 0..2047
            int r = idx >> 5, c = idx & 31;
            xs[r][c] = x[(size_t)(row0 + r) * CDIM + c0 + c];
        }
        // load weight tiles 32x64 each (coalesced)
#pragma unroll
        for (int t = 0; t < 8; t++) {
            int idx = tid + t * 256;          // 0..2047
            int cc = idx >> 6, col = idx & 63;
            ws[0][cc][col] = Wk[(c0 + cc) * HDIM + col];
            ws[1][cc][col] = Wq[(c0 + cc) * HDIM + col];
            ws[2][cc][col] = Wv[(c0 + cc) * HDIM + col];
        }
        __syncthreads();

#pragma unroll 8
        for (int cc = 0; cc < 32; cc++) {
            float af[4];
#pragma unroll
            for (int i = 0; i < 4; i++) af[i] = xs[ty * 4 + i][cc];
#pragma unroll
            for (int w = 0; w < 3; w++) {
                float4 b4 = *(const float4*)&ws[w][cc][tx * 4];
                const float bf[4] = {b4.x, b4.y, b4.z, b4.w};
#pragma unroll
                for (int i = 0; i < 4; i++)
#pragma unroll
                    for (int j = 0; j < 4; j++)
                        acc[w][i][j] += af[i] * bf[j];
            }
        }
        __syncthreads();
    }

    // write k, q (scaled by H^-0.5 = 0.125), v
#pragma unroll
    for (int i = 0; i < 4; i++) {
        size_t off = (size_t)(row0 + ty * 4 + i) * HDIM + tx * 4;
        float4 kv = make_float4(acc[0][i][0], acc[0][i][1], acc[0][i][2], acc[0][i][3]);
        float4 qv = make_float4(acc[1][i][0] * 0.125f, acc[1][i][1] * 0.125f,
                                acc[1][i][2] * 0.125f, acc[1][i][3] * 0.125f);
        float4 vv = make_float4(acc[2][i][0], acc[2][i][1], acc[2][i][2], acc[2][i][3]);
        *(float4*)&g_k[off] = kv;
        *(float4*)&g_q[off] = qv;
        *(float4*)&g_v[off] = vv;
    }
}

// ---------------------------------------------------------------------------
// Flash attention (causal).  One block per (batch, 64-query tile).
// 256 threads; thread (ty,tx) owns a 4x4 tile; tx group (16 lanes) shares rows
// so softmax reductions are 16-lane shuffles.
// smem (dynamic, 68 KB): qst/kst transposed [h][r] stride 68, pst transposed
// [s][r] stride 68, vs [s][h] stride 68 -> float4 reads 2-phase conflict-free.
// ---------------------------------------------------------------------------
#define ATT_SMEM (4 * 64 * 68 * (int)sizeof(float))

__global__ __launch_bounds__(256) void attn_kernel(float* __restrict__ out)
{
    extern __shared__ __align__(16) float sm[];
    float* qst = sm;                 // [h*68 + r]
    float* kst = sm + 64 * 68;       // [h*68 + s]
    float* pst = sm + 2 * 64 * 68;   // [s*68 + r]
    float* vs  = sm + 3 * 64 * 68;   // [s*68 + h]

    const int tid = threadIdx.x;
    const int tx = tid & 15;
    const int ty = tid >> 4;
    const int qt = (gridDim.x - 1) - blockIdx.x;   // heavy tiles first
    const int b  = blockIdx.y;
    const int qrow0 = qt * 64;
    const size_t base = (size_t)b * SEQ * HDIM;

    // load q tile transposed: warp lanes span r (conflict-free transposed store)
#pragma unroll
    for (int t = 0; t < 4; t++) {
        int fidx = tid + t * 256;        // 0..1023
        int r = fidx & 63;
        int h4 = (fidx >> 6) * 4;
        float4 qv = *(const float4*)&g_q[base + (size_t)(qrow0 + r) * HDIM + h4];
        qst[(h4 + 0) * 68 + r] = qv.x;
        qst[(h4 + 1) * 68 + r] = qv.y;
        qst[(h4 + 2) * 68 + r] = qv.z;
        qst[(h4 + 3) * 68 + r] = qv.w;
    }

    float m[4], l[4], o[4][4];
#pragma unroll
    for (int i = 0; i < 4; i++) {
        m[i] = -CUDART_INF_F;
        l[i] = 0.f;
#pragma unroll
        for (int j = 0; j < 4; j++) o[i][j] = 0.f;
    }

    for (int kt = 0; kt <= qt; kt++) {
        __syncthreads();   // previous iter's GEMM2 fully drained before overwrite

        // load k transposed + v natural
#pragma unroll
        for (int t = 0; t < 4; t++) {
            int fidx = tid + t * 256;
            int s = fidx & 63;
            int h4 = (fidx >> 6) * 4;
            float4 kv = *(const float4*)&g_k[base + (size_t)(kt * 64 + s) * HDIM + h4];
            kst[(h4 + 0) * 68 + s] = kv.x;
            kst[(h4 + 1) * 68 + s] = kv.y;
            kst[(h4 + 2) * 68 + s] = kv.z;
            kst[(h4 + 3) * 68 + s] = kv.w;
        }
#pragma unroll
        for (int t = 0; t < 4; t++) {
            int fidx = tid + t * 256;
            int h4 = (fidx & 15) * 4;
            int s = fidx >> 4;
            float4 vv = *(const float4*)&g_v[base + (size_t)(kt * 64 + s) * HDIM + h4];
            *(float4*)&vs[s * 68 + h4] = vv;
        }
        __syncthreads();

        // GEMM1: S = q @ k^T  (q pre-scaled)
        float sacc[4][4];
#pragma unroll
        for (int i = 0; i < 4; i++)
#pragma unroll
            for (int j = 0; j < 4; j++) sacc[i][j] = 0.f;

#pragma unroll 16
        for (int h = 0; h < 64; h++) {
            float4 a4 = *(const float4*)&qst[h * 68 + ty * 4];
            float4 b4 = *(const float4*)&kst[h * 68 + tx * 4];
            const float af[4] = {a4.x, a4.y, a4.z, a4.w};
            const float bf[4] = {b4.x, b4.y, b4.z, b4.w};
#pragma unroll
            for (int i = 0; i < 4; i++)
#pragma unroll
                for (int j = 0; j < 4; j++)
                    sacc[i][j] += af[i] * bf[j];
        }

        // causal mask on diagonal tile
        if (kt == qt) {
#pragma unroll
            for (int i = 0; i < 4; i++)
#pragma unroll
                for (int j = 0; j < 4; j++)
                    if (tx * 4 + j > ty * 4 + i) sacc[i][j] = -CUDART_INF_F;
        }

        // online softmax: row stats via 16-lane shuffles
        float p[4][4];
#pragma unroll
        for (int i = 0; i < 4; i++) {
            float r = fmaxf(fmaxf(sacc[i][0], sacc[i][1]),
                            fmaxf(sacc[i][2], sacc[i][3]));
#pragma unroll
            for (int off = 8; off > 0; off >>= 1)
                r = fmaxf(r, __shfl_xor_sync(0xffffffffu, r, off, 16));
            float mn = fmaxf(m[i], r);
            float alpha = __expf(m[i] - mn);   // exp(-inf)=0 on first tile
            m[i] = mn;
            float rsum = 0.f;
#pragma unroll
            for (int j = 0; j < 4; j++) {
                p[i][j] = __expf(sacc[i][j] - mn);
                rsum += p[i][j];
            }
#pragma unroll
            for (int off = 8; off > 0; off >>= 1)
                rsum += __shfl_xor_sync(0xffffffffu, rsum, off, 16);
            l[i] = l[i] * alpha + rsum;
#pragma unroll
            for (int j = 0; j < 4; j++) o[i][j] *= alpha;
        }

        // write P transposed [s][r] (float4 over r)
#pragma unroll
        for (int j = 0; j < 4; j++) {
            float4 pv = make_float4(p[0][j], p[1][j], p[2][j], p[3][j]);
            *(float4*)&pst[(tx * 4 + j) * 68 + ty * 4] = pv;
        }
        __syncthreads();

        // GEMM2: O += P @ V
#pragma unroll 16
        for (int s = 0; s < 64; s++) {
            float4 p4 = *(const float4*)&pst[s * 68 + ty * 4];
            float4 v4 = *(const float4*)&vs[s * 68 + tx * 4];
            const float pf[4] = {p4.x, p4.y, p4.z, p4.w};
            const float vf[4] = {v4.x, v4.y, v4.z, v4.w};
#pragma unroll
            for (int i = 0; i < 4; i++)
#pragma unroll
                for (int j = 0; j < 4; j++)
                    o[i][j] += pf[i] * vf[j];
        }
    }

    // epilogue: normalize and store
#pragma unroll
    for (int i = 0; i < 4; i++) {
        float inv = 1.f / l[i];
        float4 ov = make_float4(o[i][0] * inv, o[i][1] * inv,
                                o[i][2] * inv, o[i][3] * inv);
        *(float4*)&out[base + (size_t)(qrow0 + ty * 4 + i) * HDIM + tx * 4] = ov;
    }
}

// ---------------------------------------------------------------------------
extern "C" void kernel_launch(void* const* d_in, const int* in_sizes, int n_in,
                              void* d_out, int out_size)
{
    const float* x  = (const float*)d_in[0];
    const float* Wk = (const float*)d_in[1];
    const float* Wq = (const float*)d_in[2];
    const float* Wv = (const float*)d_in[3];
    float* out = (float*)d_out;

    proj_kernel<<<M_TOT / 64, 256>>>(x, Wk, Wq, Wv);

    cudaFuncSetAttribute(attn_kernel, cudaFuncAttributeMaxDynamicSharedMemorySize,
                         ATT_SMEM);
    dim3 grid(SEQ / 64, BATCH);
    attn_kernel<<<grid, 256, ATT_SMEM>>>(out);
}